// round 16
// baseline (speedup 1.0000x reference)
#include <cuda_runtime.h>
#include <cuda_fp16.h>
#include <math.h>
#include <stdint.h>

#define B_SZ 2
#define S_LEN 2048
#define HID 2048
#define NH 16
#define NKV 4
#define HD 128
#define M_TOK (B_SZ * S_LEN)   // 4096

// ---------------- scratch ----------------------------------------------------
__device__ float  g_g1[M_TOK * NH];
__device__ float  g_g2[M_TOK * NH];
__device__ float  g_cosT[S_LEN * 64];
__device__ float  g_sinT[S_LEN * 64];
__device__ __half g_hidden_h[M_TOK * HID];
__device__ __half g_Wq_h[HID * 2048];
__device__ __half g_Wk_h[HID * 512];
__device__ __half g_Wv_h[HID * 512];
__device__ __half g_Wo_h[2048 * 2048];
__device__ __half g_Wg_h[HID * 32];         // packed Wg1|Wg2, k-pair interleaved
__device__ __half g_qh[M_TOK * NH * HD];
__device__ __half g_kh[M_TOK * NKV * HD];
__device__ __half g_vh[M_TOK * NKV * HD];   // [b*NKV+kvh][s/2][d][2]
__device__ __half g_att_h[M_TOK * NH * HD];

// ---------------- helpers ----------------------------------------------------
__device__ __forceinline__ void mma16(float c[4], const uint32_t a[4],
                                      uint32_t b0, uint32_t b1) {
    asm volatile(
        "mma.sync.aligned.m16n8k16.row.col.f32.f16.f16.f32 "
        "{%0,%1,%2,%3}, {%4,%5,%6,%7}, {%8,%9}, {%0,%1,%2,%3};\n"
        : "+f"(c[0]), "+f"(c[1]), "+f"(c[2]), "+f"(c[3])
        : "r"(a[0]), "r"(a[1]), "r"(a[2]), "r"(a[3]), "r"(b0), "r"(b1));
}
__device__ __forceinline__ uint32_t h2u(__half2 h) {
    return *reinterpret_cast<uint32_t*>(&h);
}
__device__ __forceinline__ uint32_t smaddr(const void* p) {
    return (uint32_t)__cvta_generic_to_shared(p);
}
#define CP16(dst, src) \
    asm volatile("cp.async.cg.shared.global [%0], [%1], 16;\n" :: "r"(dst), "l"(src))
#define CP4(dst, src)  \
    asm volatile("cp.async.ca.shared.global [%0], [%1], 4;\n"  :: "r"(dst), "l"(src))
#define CPCOMMIT() asm volatile("cp.async.commit_group;\n")
#define CPWAIT0()  asm volatile("cp.async.wait_group 0;\n")
#define CPWAIT1()  asm volatile("cp.async.wait_group 1;\n")

// ---------------- fused conversion + rope-table kernel -----------------------
__device__ __forceinline__ void kpair_one(const float* __restrict__ W,
                                          __half* __restrict__ Wh, int N, int i)
{
    int kk = i / N, n = i - kk * N;
    ((__half2*)Wh)[(size_t)kk * N + n] = __floats2half2_rn(
        W[(size_t)(2 * kk) * N + n], W[(size_t)(2 * kk + 1) * N + n]);
}

// grid 29312 x 256; all section sizes are exact multiples of 256.
__global__ void conv_all(
    const float* __restrict__ hidden, const float* __restrict__ Wq,
    const float* __restrict__ Wk, const float* __restrict__ Wv,
    const float* __restrict__ Wo, const float* __restrict__ Wg1,
    const float* __restrict__ Wg2, const int* __restrict__ pos,
    __half* __restrict__ hh, __half* __restrict__ wqh, __half* __restrict__ wkh,
    __half* __restrict__ wvh, __half* __restrict__ woh, __half* __restrict__ wgh,
    float* __restrict__ cosT, float* __restrict__ sinT)
{
    int bid = blockIdx.x, tid = threadIdx.x;
    if (bid < 8192) {                          // hidden fp32 -> fp16 natural
        int i = bid * 256 + tid;               // 2,097,152 float4
        float4 v = ((const float4*)hidden)[i];
        __half2* o = (__half2*)hh + (size_t)i * 2;
        o[0] = __floats2half2_rn(v.x, v.y);
        o[1] = __floats2half2_rn(v.z, v.w);
    } else if (bid < 16384) {                  // Wq k-pair
        kpair_one(Wq, wqh, 2048, (bid - 8192) * 256 + tid);
    } else if (bid < 18432) {                  // Wk
        kpair_one(Wk, wkh, 512, (bid - 16384) * 256 + tid);
    } else if (bid < 20480) {                  // Wv
        kpair_one(Wv, wvh, 512, (bid - 18432) * 256 + tid);
    } else if (bid < 28672) {                  // Wo
        kpair_one(Wo, woh, 2048, (bid - 20480) * 256 + tid);
    } else if (bid < 28800) {                  // gates pack: 128 blocks
        int i = (bid - 28672) * 256 + tid;
        int kk = i >> 5, n = i & 31;
        const float* W = (n < 16) ? Wg1 : Wg2;
        int col = n & 15;
        ((__half2*)wgh)[(size_t)kk * 32 + n] = __floats2half2_rn(
            W[(size_t)(2 * kk) * 16 + col], W[(size_t)(2 * kk + 1) * 16 + col]);
    } else {                                   // rope table: 512 blocks, 131072
        int idx = (bid - 28800) * 256 + tid;
        int s = idx >> 6, i = idx & 63;
        double p    = (double)pos[s];
        double invf = exp(-((double)i / 64.0) * log(10000.0));
        double ang  = p * invf;
        cosT[idx] = (float)cos(ang);
        sinT[idx] = (float)sin(ang);
    }
}

// ---------------- fp16 GEMM: C = A(Mx2048) @ W(2048xN) ----------------------
// BM=128 BN=128 BK=32, 4 warps (2x2), warp tile 64x64, mma m16n8k16
// stage (h2 words): A [128][20], B [16][136]. GSTG=4736 w.
#define GSTG 4736

__device__ __forceinline__ void gemm_issue_h(
    const __half* __restrict__ A, const __half* __restrict__ Wh,
    uint32_t* sa, int N, size_t m0, size_t n0, int k0, int tid)
{
    uint32_t* sb = sa + 2560;
#pragma unroll
    for (int j = 0; j < 4; j++) {                 // A: 512 CP16, 128 threads
        int idx = tid + j * 128;
        int r = idx >> 2, q = idx & 3;
        CP16(smaddr(sa + r * 20 + q * 4), A + (m0 + r) * HID + k0 + q * 8);
    }
#pragma unroll
    for (int j = 0; j < 4; j++) {                 // B: 512 CP16
        int idx = tid + j * 128;
        int r = idx >> 5, cc = idx & 31;
        CP16(smaddr(sb + r * 136 + cc * 4),
             Wh + ((size_t)((k0 >> 1) + r) * N + n0 + cc * 4) * 2);
    }
}

// MODE 0: C f32 natural. MODE 1: C half natural. MODE 2: C half V-interleaved.
template <int MODE>
__device__ __forceinline__ void gemm_body_h(
    const __half* __restrict__ A, const __half* __restrict__ Wh, void* Cv,
    int N, size_t m0, size_t n0, uint32_t* sm)
{
    const int tid  = threadIdx.x;
    const int lane = tid & 31;
    const int wid  = tid >> 5;          // 0..3
    const int g    = lane >> 2;
    const int c    = lane & 3;
    const int wm   = (wid >> 1) * 64;
    const int wn   = (wid & 1) * 64;

    float acc[4][8][4];
#pragma unroll
    for (int i = 0; i < 4; i++)
#pragma unroll
        for (int j = 0; j < 8; j++)
#pragma unroll
            for (int r = 0; r < 4; r++) acc[i][j][r] = 0.f;

    const int NIT = HID / 32;   // 64
    gemm_issue_h(A, Wh, sm + 0 * GSTG, N, m0, n0, 0, tid);  CPCOMMIT();
    gemm_issue_h(A, Wh, sm + 1 * GSTG, N, m0, n0, 32, tid); CPCOMMIT();

    for (int i = 0; i < NIT; i++) {
        CPWAIT1();
        __syncthreads();
        if (i + 2 < NIT)
            gemm_issue_h(A, Wh, sm + ((i + 2) % 3) * GSTG, N, m0, n0,
                         (i + 2) * 32, tid);
        CPCOMMIT();

        const uint32_t* sa = sm + (i % 3) * GSTG;
        const uint32_t* sb = sa + 2560;
#pragma unroll
        for (int kb = 0; kb < 2; kb++) {
            uint32_t af[4][4], bf[8][2];
#pragma unroll
            for (int mt = 0; mt < 4; mt++) {
                const uint32_t* ap = sa + (wm + mt * 16 + g) * 20 + kb * 8 + c;
                af[mt][0] = ap[0];
                af[mt][1] = ap[8 * 20];
                af[mt][2] = ap[4];
                af[mt][3] = ap[8 * 20 + 4];
            }
#pragma unroll
            for (int nt = 0; nt < 8; nt++) {
                const uint32_t* bp = sb + (kb * 8 + c) * 136 + wn + nt * 8 + g;
                bf[nt][0] = bp[0];
                bf[nt][1] = bp[4 * 136];
            }
#pragma unroll
            for (int mt = 0; mt < 4; mt++)
#pragma unroll
                for (int nt = 0; nt < 8; nt++)
                    mma16(acc[mt][nt], af[mt], bf[nt][0], bf[nt][1]);
        }
    }

    if (MODE == 0) {
        float* C = (float*)Cv;
#pragma unroll
        for (int mt = 0; mt < 4; mt++)
#pragma unroll
            for (int nt = 0; nt < 8; nt++) {
                size_t r  = m0 + wm + mt * 16 + g;
                size_t cc = n0 + wn + nt * 8 + 2 * c;
                *(float2*)&C[r * N + cc] =
                    make_float2(acc[mt][nt][0], acc[mt][nt][1]);
                *(float2*)&C[(r + 8) * N + cc] =
                    make_float2(acc[mt][nt][2], acc[mt][nt][3]);
            }
    } else if (MODE == 1) {
        __half* C = (__half*)Cv;
#pragma unroll
        for (int mt = 0; mt < 4; mt++)
#pragma unroll
            for (int nt = 0; nt < 8; nt++) {
                size_t r  = m0 + wm + mt * 16 + g;
                size_t cc = n0 + wn + nt * 8 + 2 * c;
                *(__half2*)&C[r * N + cc] =
                    __floats2half2_rn(acc[mt][nt][0], acc[mt][nt][1]);
                *(__half2*)&C[(r + 8) * N + cc] =
                    __floats2half2_rn(acc[mt][nt][2], acc[mt][nt][3]);
            }
    } else {
        __half* C = (__half*)Cv;
#pragma unroll
        for (int mt = 0; mt < 4; mt++)
#pragma unroll
            for (int nt = 0; nt < 8; nt++) {
                int ng  = (int)n0 + wn + nt * 8 + 2 * c;
                int kvh = ng >> 7, d = ng & 127;
#pragma unroll
                for (int p = 0; p < 2; p++) {
                    size_t tok = m0 + wm + mt * 16 + g + p * 8;
                    int b = (int)(tok >> 11), s = (int)(tok & 2047);
                    size_t base =
                        (((size_t)(b * NKV + kvh) * 1024 + (s >> 1)) * 128 + d) * 2
                        + (s & 1);
                    C[base]     = __float2half(acc[mt][nt][p * 2 + 0]);
                    C[base + 2] = __float2half(acc[mt][nt][p * 2 + 1]);
                }
            }
    }
}

// ---------------- gates body (128 threads, merged into qkv grid) -------------
__device__ __forceinline__ void gates_issue128(
    const __half* __restrict__ hh, const __half* __restrict__ WgT,
    uint32_t* sa, size_t m0, int k0, int tid)
{
    uint32_t* sb = sa + 2560;
#pragma unroll
    for (int j = 0; j < 4; j++) {                 // A: 512 CP16
        int idx = tid + j * 128;
        int r = idx >> 2, q = idx & 3;
        CP16(smaddr(sa + r * 20 + q * 4), hh + (m0 + r) * HID + k0 + q * 8);
    }
    {                                             // B: 128 CP16 ([16][32] h2)
        int r = tid >> 3, cc = tid & 7;
        CP16(smaddr(sb + r * 136 + cc * 4),
             WgT + ((size_t)((k0 >> 1) + r) * 32 + cc * 4) * 2);
    }
}

__device__ __forceinline__ void gates_body(
    const __half* __restrict__ hh, const __half* __restrict__ WgT,
    const float* __restrict__ bg1, const float* __restrict__ bg2,
    float* __restrict__ g1, float* __restrict__ g2,
    size_t m0, uint32_t* sm)
{
    const int tid  = threadIdx.x;
    const int lane = tid & 31;
    const int wid  = tid >> 5;          // 0..3, warp = 32 tokens (2 m-tiles)
    const int g    = lane >> 2;
    const int c    = lane & 3;

    float acc[2][4][4];
#pragma unroll
    for (int mt = 0; mt < 2; mt++)
#pragma unroll
        for (int j = 0; j < 4; j++)
#pragma unroll
            for (int r = 0; r < 4; r++) acc[mt][j][r] = 0.f;

    const int NIT = HID / 32;   // 64
    gates_issue128(hh, WgT, sm + 0 * GSTG, m0, 0, tid);  CPCOMMIT();
    gates_issue128(hh, WgT, sm + 1 * GSTG, m0, 32, tid); CPCOMMIT();

    for (int i = 0; i < NIT; i++) {
        CPWAIT1();
        __syncthreads();
        if (i + 2 < NIT)
            gates_issue128(hh, WgT, sm + ((i + 2) % 3) * GSTG, m0,
                           (i + 2) * 32, tid);
        CPCOMMIT();

        const uint32_t* sa = sm + (i % 3) * GSTG;
        const uint32_t* sb = sa + 2560;
#pragma unroll
        for (int kb = 0; kb < 2; kb++) {
#pragma unroll
            for (int mt = 0; mt < 2; mt++) {
                uint32_t af[4];
                const uint32_t* ap =
                    sa + (wid * 32 + mt * 16 + g) * 20 + kb * 8 + c;
                af[0] = ap[0];
                af[1] = ap[8 * 20];
                af[2] = ap[4];
                af[3] = ap[8 * 20 + 4];
#pragma unroll
                for (int nt = 0; nt < 4; nt++) {
                    const uint32_t* bp = sb + (kb * 8 + c) * 136 + nt * 8 + g;
                    mma16(acc[mt][nt], af, bp[0], bp[4 * 136]);
                }
            }
        }
    }

#pragma unroll
    for (int mt = 0; mt < 2; mt++)
#pragma unroll
        for (int nt = 0; nt < 4; nt++)
#pragma unroll
            for (int half = 0; half < 2; half++) {
                int n = nt * 8 + 2 * c + half;
                float b = (n < 16) ? bg1[n] : bg2[n - 16];
#pragma unroll
                for (int p = 0; p < 2; p++) {
                    size_t tok = m0 + wid * 32 + mt * 16 + g + p * 8;
                    float v = 1.f / (1.f + __expf(-(acc[mt][nt][p * 2 + half] + b)));
                    if (n < 16) g1[tok * NH + n]        = v;
                    else        g2[tok * NH + (n - 16)] = v;
                }
            }
}

// fused QKV + gates: grid (25, 32), 128 threads
__global__ __launch_bounds__(128, 2) void qkv_kernel(
    const __half* __restrict__ hidden_h,
    const __half* __restrict__ Wq_h, const __half* __restrict__ Wk_h,
    const __half* __restrict__ Wv_h, const __half* __restrict__ Wg_h,
    const float* __restrict__ bg1, const float* __restrict__ bg2,
    __half* __restrict__ qh, __half* __restrict__ kh, __half* __restrict__ vh,
    float* __restrict__ g1, float* __restrict__ g2)
{
    extern __shared__ uint32_t gsm[];
    int bx = blockIdx.x;
    size_t m0 = (size_t)blockIdx.y * 128;
    if (bx < 16)
        gemm_body_h<1>(hidden_h, Wq_h, qh, 2048, m0, (size_t)bx * 128, gsm);
    else if (bx < 20)
        gemm_body_h<1>(hidden_h, Wk_h, kh, 512, m0, (size_t)(bx - 16) * 128, gsm);
    else if (bx < 24)
        gemm_body_h<2>(hidden_h, Wv_h, vh, 512, m0, (size_t)(bx - 20) * 128, gsm);
    else
        gates_body(hidden_h, Wg_h, bg1, bg2, g1, g2, m0, gsm);
}

__global__ __launch_bounds__(128, 2) void out_kernel(
    const __half* __restrict__ att_h, const __half* __restrict__ Wo_h,
    float* __restrict__ out)
{
    extern __shared__ uint32_t gsm[];
    gemm_body_h<0>(att_h, Wo_h, out, 2048, (size_t)blockIdx.y * 128,
                   (size_t)blockIdx.x * 128, gsm);
}

// ---------------- vectorized in-place fp16 RoPE (8 elems/thread) -------------
__global__ void rope_inplace_h(__half* __restrict__ x,
                               const float* __restrict__ cosT,
                               const float* __restrict__ sinT, int heads)
{
    int idx = blockIdx.x * blockDim.x + threadIdx.x;   // M_TOK*heads*16
    int total = M_TOK * heads * 16;
    if (idx >= total) return;
    int i4 = (idx & 15) * 4;
    int h  = (idx >> 4) % heads;
    int m  = idx / (heads * 16);
    int s  = m & (S_LEN - 1);
    float4 cv = *(const float4*)&cosT[s * 64 + i4];
    float4 sn = *(const float4*)&sinT[s * 64 + i4];
    __half* p = x + ((size_t)m * heads + h) * HD;
    __half2 lo0 = *(__half2*)&p[i4],      lo1 = *(__half2*)&p[i4 + 2];
    __half2 hi0 = *(__half2*)&p[i4 + 64], hi1 = *(__half2*)&p[i4 + 66];
    float a0 = __half2float(lo0.x), a1 = __half2float(lo0.y);
    float a2 = __half2float(lo1.x), a3 = __half2float(lo1.y);
    float b0 = __half2float(hi0.x), b1 = __half2float(hi0.y);
    float b2 = __half2float(hi1.x), b3 = __half2float(hi1.y);
    *(__half2*)&p[i4]      = __floats2half2_rn(a0 * cv.x - b0 * sn.x,
                                               a1 * cv.y - b1 * sn.y);
    *(__half2*)&p[i4 + 2]  = __floats2half2_rn(a2 * cv.z - b2 * sn.z,
                                               a3 * cv.w - b3 * sn.w);
    *(__half2*)&p[i4 + 64] = __floats2half2_rn(b0 * cv.x + a0 * sn.x,
                                               b1 * cv.y + a1 * sn.y);
    *(__half2*)&p[i4 + 66] = __floats2half2_rn(b2 * cv.z + a2 * sn.z,
                                               b3 * cv.w + a3 * sn.w);
}

// ---------------- fp16 flash attention (P in registers) ----------------------
// smem h2 words: stage s in {0,1}: K at s*8704 ([64][68]), V at +4352 ([32][136])
// g2 f32 at 17408 ([2][64]).  total 17536 w = 70144 B.
__device__ __forceinline__ void kv_issue_h(
    const __half* __restrict__ kh, const __half* __restrict__ vh,
    const float* __restrict__ g2, uint32_t* smw, int stage,
    int b, int kt, int kvh, int h, int tid)
{
    uint32_t* Kst = smw + stage * 8704;
    uint32_t* Vst = Kst + 4352;
    float*    g2d = (float*)(smw + 17408) + stage * 64;
#pragma unroll
    for (int j = 0; j < 4; j++) {
        int idx = tid + j * 256;
        int r = idx >> 4, cc = idx & 15;
        size_t tok = (size_t)(b * S_LEN + kt * 64 + r);
        CP16(smaddr(Kst + r * 68 + cc * 4), kh + (tok * NKV + kvh) * HD + cc * 8);
    }
#pragma unroll
    for (int j = 0; j < 4; j++) {
        int idx = tid + j * 256;
        int r = idx >> 5, cc = idx & 31;
        size_t sp = (size_t)(b * NKV + kvh) * 1024 + kt * 32 + r;
        CP16(smaddr(Vst + r * 136 + cc * 4), vh + sp * 256 + cc * 8);
    }
    if (tid < 64) {
        size_t tok = (size_t)(b * S_LEN + kt * 64 + tid);
        CP4(smaddr(g2d + tid), g2 + tok * NH + h);
    }
}

__global__ __launch_bounds__(256) void flash_h(
    const __half* __restrict__ qh, const __half* __restrict__ kh,
    const __half* __restrict__ vh,
    const float* __restrict__ g1, const float* __restrict__ g2,
    const float* __restrict__ gamma, const float* __restrict__ beta,
    __half* __restrict__ att)
{
    const int qt  = (int)(gridDim.x - 1 - blockIdx.x);   // LPT: big blocks first
    const int bh  = blockIdx.y;
    const int b   = bh >> 4;
    const int h   = bh & 15;
    const int kvh = h >> 2;
    const int tid = threadIdx.x;
    const int lane = tid & 31;
    const int wid  = tid >> 5;
    const int g    = lane >> 2;
    const int c    = lane & 3;
    const int q0   = qt * 128;

    extern __shared__ uint32_t smw[];

    const float scale = 0.08838834764831845f;
    const int nkt = 2 * (qt + 1);

    kv_issue_h(kh, vh, g2, smw, 0, b, 0, kvh, h, tid);
    CPCOMMIT();
    {
        uint32_t* Qt = smw + 8704;          // [128][68] h2 (stage-1 region)
#pragma unroll
        for (int j = 0; j < 8; j++) {
            int idx = tid + j * 256;
            int r = idx >> 4, cc = idx & 15;
            CP16(smaddr(Qt + r * 68 + cc * 4),
                 qh + ((size_t)(b * S_LEN + q0 + r) * NH + h) * HD + cc * 8);
        }
    }
    CPCOMMIT();
    CPWAIT0();
    __syncthreads();

    uint32_t qf[8][4];
    {
        const uint32_t* Qt = smw + 8704;
#pragma unroll
        for (int kb = 0; kb < 8; kb++) {
            const uint32_t* qp = Qt + (wid * 16 + g) * 68 + kb * 8 + c;
            qf[kb][0] = qp[0];
            qf[kb][1] = qp[8 * 68];
            qf[kb][2] = qp[4];
            qf[kb][3] = qp[8 * 68 + 4];
        }
    }
    __syncthreads();

    float oacc[16][4];
#pragma unroll
    for (int nt = 0; nt < 16; nt++)
#pragma unroll
        for (int r = 0; r < 4; r++) oacc[nt][r] = 0.f;
    float m_r0 = -1e30f, m_r1 = -1e30f, l_r0 = 0.f, l_r1 = 0.f;

    for (int kt = 0; kt < nkt; kt++) {
        if (kt + 1 < nkt)
            kv_issue_h(kh, vh, g2, smw, (kt + 1) & 1, b, kt + 1, kvh, h, tid);
        CPCOMMIT();

        const uint32_t* Kst = smw + (kt & 1) * 8704;
        const uint32_t* Vst = Kst + 4352;
        const float*    g2p = (const float*)(smw + 17408) + (kt & 1) * 64;
        const int k0 = kt * 64;

        float s[8][4];
#pragma unroll
        for (int nt = 0; nt < 8; nt++)
#pragma unroll
            for (int r = 0; r < 4; r++) s[nt][r] = 0.f;
#pragma unroll
        for (int kb = 0; kb < 8; kb++)
#pragma unroll
            for (int nt = 0; nt < 8; nt++) {
                const uint32_t* kp = Kst + (nt * 8 + g) * 68 + kb * 8 + c;
                mma16(s[nt], qf[kb], kp[0], kp[4]);
            }
#pragma unroll
        for (int nt = 0; nt < 8; nt++)
#pragma unroll
            for (int r = 0; r < 4; r++) s[nt][r] *= scale;

        if (kt >= 2 * qt) {
            const int r0 = q0 + wid * 16 + g, r1 = r0 + 8;
#pragma unroll
            for (int nt = 0; nt < 8; nt++) {
                int col = k0 + nt * 8 + 2 * c;
                if (col     > r0) s[nt][0] = -1e30f;
                if (col + 1 > r0) s[nt][1] = -1e30f;
                if (col     > r1) s[nt][2] = -1e30f;
                if (col + 1 > r1) s[nt][3] = -1e30f;
            }
        }

        float mx0 = -1e30f, mx1 = -1e30f;
#pragma unroll
        for (int nt = 0; nt < 8; nt++) {
            mx0 = fmaxf(mx0, fmaxf(s[nt][0], s[nt][1]));
            mx1 = fmaxf(mx1, fmaxf(s[nt][2], s[nt][3]));
        }
#pragma unroll
        for (int off = 1; off <= 2; off <<= 1) {
            mx0 = fmaxf(mx0, __shfl_xor_sync(0xffffffffu, mx0, off));
            mx1 = fmaxf(mx1, __shfl_xor_sync(0xffffffffu, mx1, off));
        }
        float mn0 = fmaxf(m_r0, mx0), mn1 = fmaxf(m_r1, mx1);
        float sum0 = 0.f, sum1 = 0.f;
#pragma unroll
        for (int nt = 0; nt < 8; nt++) {
            s[nt][0] = __expf(s[nt][0] - mn0);
            s[nt][1] = __expf(s[nt][1] - mn0);
            s[nt][2] = __expf(s[nt][2] - mn1);
            s[nt][3] = __expf(s[nt][3] - mn1);
            sum0 += s[nt][0] + s[nt][1];
            sum1 += s[nt][2] + s[nt][3];
        }
#pragma unroll
        for (int off = 1; off <= 2; off <<= 1) {
            sum0 += __shfl_xor_sync(0xffffffffu, sum0, off);
            sum1 += __shfl_xor_sync(0xffffffffu, sum1, off);
        }
        float a0 = __expf(m_r0 - mn0), a1 = __expf(m_r1 - mn1);
        m_r0 = mn0; m_r1 = mn1;
        l_r0 = l_r0 * a0 + sum0;
        l_r1 = l_r1 * a1 + sum1;
#pragma unroll
        for (int nt = 0; nt < 16; nt++) {
            oacc[nt][0] *= a0; oacc[nt][1] *= a0;
            oacc[nt][2] *= a1; oacc[nt][3] *= a1;
        }

        // ---- O += P @ V, P packed directly from s-registers (g2 folded) ----
#pragma unroll
        for (int kb = 0; kb < 4; kb++) {
            int col0 = kb * 16 + 2 * c;
            float w00 = g2p[col0],     w01 = g2p[col0 + 1];
            float w10 = g2p[col0 + 8], w11 = g2p[col0 + 9];
            uint32_t pf[4];
            pf[0] = h2u(__floats2half2_rn(s[2 * kb][0] * w00, s[2 * kb][1] * w01));
            pf[1] = h2u(__floats2half2_rn(s[2 * kb][2] * w00, s[2 * kb][3] * w01));
            pf[2] = h2u(__floats2half2_rn(s[2 * kb + 1][0] * w10,
                                          s[2 * kb + 1][1] * w11));
            pf[3] = h2u(__floats2half2_rn(s[2 * kb + 1][2] * w10,
                                          s[2 * kb + 1][3] * w11));
#pragma unroll 8
            for (int nt = 0; nt < 16; nt++) {
                const uint32_t* vp = Vst + (kb * 8 + c) * 136 + nt * 8 + g;
                mma16(oacc[nt], pf, vp[0], vp[4 * 136]);
            }
        }

        if (kt + 1 < nkt) {
            CPWAIT0();
            __syncthreads();
        }
    }
    __syncthreads();

    // ---- stage gamma/beta (reuse stage-0 smem) ----
    float* gb = (float*)smw;
    if (tid < 128) {
        gb[tid]       = gamma[tid];
        gb[128 + tid] = beta[tid];
    }
    __syncthreads();

    float inv0 = 1.f / l_r0, inv1 = 1.f / l_r1;
    float su0 = 0.f, sq0 = 0.f, su1 = 0.f, sq1 = 0.f;
#pragma unroll
    for (int nt = 0; nt < 16; nt++) {
        oacc[nt][0] *= inv0; oacc[nt][1] *= inv0;
        oacc[nt][2] *= inv1; oacc[nt][3] *= inv1;
        su0 += oacc[nt][0] + oacc[nt][1];
        sq0 += oacc[nt][0] * oacc[nt][0] + oacc[nt][1] * oacc[nt][1];
        su1 += oacc[nt][2] + oacc[nt][3];
        sq1 += oacc[nt][2] * oacc[nt][2] + oacc[nt][3] * oacc[nt][3];
    }
#pragma unroll
    for (int off = 1; off <= 2; off <<= 1) {
        su0 += __shfl_xor_sync(0xffffffffu, su0, off);
        sq0 += __shfl_xor_sync(0xffffffffu, sq0, off);
        su1 += __shfl_xor_sync(0xffffffffu, su1, off);
        sq1 += __shfl_xor_sync(0xffffffffu, sq1, off);
    }
    float mu0 = su0 * (1.f / 128.f), mu1 = su1 * (1.f / 128.f);
    float rs0 = rsqrtf(sq0 * (1.f / 128.f) - mu0 * mu0 + 1e-5f);
    float rs1 = rsqrtf(sq1 * (1.f / 128.f) - mu1 * mu1 + 1e-5f);

    const int r0 = q0 + wid * 16 + g, r1 = r0 + 8;
    float gv0 = g1[((size_t)(b * S_LEN + r0)) * NH + h];
    float gv1 = g1[((size_t)(b * S_LEN + r1)) * NH + h];
    size_t base0 = ((size_t)(b * S_LEN + r0)) * (NH * HD) + h * HD;
    size_t base1 = ((size_t)(b * S_LEN + r1)) * (NH * HD) + h * HD;
#pragma unroll
    for (int nt = 0; nt < 16; nt++) {
        int col = nt * 8 + 2 * c;
        float ga = gb[col], gba = gb[128 + col];
        float gc = gb[col + 1], gbc = gb[128 + col + 1];
        *(__half2*)&att[base0 + col] = __floats2half2_rn(
            ((oacc[nt][0] - mu0) * rs0 * ga + gba) * gv0,
            ((oacc[nt][1] - mu0) * rs0 * gc + gbc) * gv0);
        *(__half2*)&att[base1 + col] = __floats2half2_rn(
            ((oacc[nt][2] - mu1) * rs1 * ga + gba) * gv1,
            ((oacc[nt][3] - mu1) * rs1 * gc + gbc) * gv1);
    }
}

// ---------------- launch ----------------------------------------------------
extern "C" void kernel_launch(void* const* d_in, const int* in_sizes, int n_in,
                              void* d_out, int out_size)
{
    const float* hidden = (const float*)d_in[0];
    const int*   pos    = (const int*)d_in[1];
    const float* Wq     = (const float*)d_in[2];
    const float* Wk     = (const float*)d_in[3];
    const float* Wv     = (const float*)d_in[4];
    const float* Wo     = (const float*)d_in[5];
    const float* Wg1    = (const float*)d_in[6];
    const float* bg1    = (const float*)d_in[7];
    const float* Wg2    = (const float*)d_in[8];
    const float* bg2    = (const float*)d_in[9];
    const float* gamma  = (const float*)d_in[10];
    const float* beta   = (const float*)d_in[11];
    float* out = (float*)d_out;

    float *g1, *g2, *cosT, *sinT;
    __half *hh, *wqh, *wkh, *wvh, *woh, *wgh, *qh, *kh, *vh, *atth;
    cudaGetSymbolAddress((void**)&g1,   g_g1);
    cudaGetSymbolAddress((void**)&g2,   g_g2);
    cudaGetSymbolAddress((void**)&cosT, g_cosT);
    cudaGetSymbolAddress((void**)&sinT, g_sinT);
    cudaGetSymbolAddress((void**)&hh,   g_hidden_h);
    cudaGetSymbolAddress((void**)&wqh,  g_Wq_h);
    cudaGetSymbolAddress((void**)&wkh,  g_Wk_h);
    cudaGetSymbolAddress((void**)&wvh,  g_Wv_h);
    cudaGetSymbolAddress((void**)&woh,  g_Wo_h);
    cudaGetSymbolAddress((void**)&wgh,  g_Wg_h);
    cudaGetSymbolAddress((void**)&qh,   g_qh);
    cudaGetSymbolAddress((void**)&kh,   g_kh);
    cudaGetSymbolAddress((void**)&vh,   g_vh);
    cudaGetSymbolAddress((void**)&atth, g_att_h);

    // 0) fused conversions + rope table
    conv_all<<<29312, 256>>>(hidden, Wq, Wk, Wv, Wo, Wg1, Wg2, pos,
                             hh, wqh, wkh, wvh, woh, wgh, cosT, sinT);

    const int gemm_smem = 3 * GSTG * 4;   // 56832 B
    cudaFuncSetAttribute(qkv_kernel, cudaFuncAttributeMaxDynamicSharedMemorySize,
                         gemm_smem);
    cudaFuncSetAttribute(out_kernel, cudaFuncAttributeMaxDynamicSharedMemorySize,
                         gemm_smem);

    // 1) fused Q/K/V projections + gates (fp16 outputs)
    qkv_kernel<<<dim3(25, 32), 128, gemm_smem>>>(
        hh, wqh, wkh, wvh, wgh, bg1, bg2, qh, kh, vh, g1, g2);

    // 2) in-place fp16 RoPE (vectorized, 8 elems/thread)
    rope_inplace_h<<<(M_TOK * NH * 16) / 256, 256>>>(qh, cosT, sinT, NH);
    rope_inplace_h<<<(M_TOK * NKV * 16) / 256, 256>>>(kh, cosT, sinT, NKV);

    // 3) fp16 flash attention (P in registers, LPT block order)
    const int flash_smem = 17536 * 4;     // 70144 B
    cudaFuncSetAttribute(flash_h, cudaFuncAttributeMaxDynamicSharedMemorySize,
                         flash_smem);
    flash_h<<<dim3(S_LEN / 128, B_SZ * NH), 256, flash_smem>>>(
        qh, kh, vh, g1, g2, gamma, beta, atth);

    // 4) output projection
    out_kernel<<<dim3(16, 32), 128, gemm_smem>>>(atth, woh, out);
}

// round 17
// speedup vs baseline: 1.8386x; 1.8386x over previous
#include <cuda_runtime.h>
#include <cuda_fp16.h>
#include <math.h>
#include <stdint.h>

#define B_SZ 2
#define S_LEN 2048
#define HID 2048
#define NH 16
#define NKV 4
#define HD 128
#define M_TOK (B_SZ * S_LEN)   // 4096

// ---------------- scratch ----------------------------------------------------
__device__ float  g_g1[M_TOK * NH];
__device__ float  g_g2[M_TOK * NH];
__device__ float  g_cosT[S_LEN * 64];
__device__ float  g_sinT[S_LEN * 64];
__device__ __half g_hidden_h[M_TOK * HID];
__device__ __half g_Wq_h[HID * 2048];
__device__ __half g_Wk_h[HID * 512];
__device__ __half g_Wv_h[HID * 512];
__device__ __half g_Wo_h[2048 * 2048];
__device__ __half g_Wg_h[HID * 32];         // packed Wg1|Wg2, k-pair interleaved
__device__ __half g_qh[M_TOK * NH * HD];
__device__ __half g_kh[M_TOK * NKV * HD];
__device__ __half g_vh[M_TOK * NKV * HD];   // [b*NKV+kvh][s/2][d][2]
__device__ __half g_att_h[M_TOK * NH * HD];

// ---------------- helpers ----------------------------------------------------
__device__ __forceinline__ void mma16(float c[4], const uint32_t a[4],
                                      uint32_t b0, uint32_t b1) {
    asm volatile(
        "mma.sync.aligned.m16n8k16.row.col.f32.f16.f16.f32 "
        "{%0,%1,%2,%3}, {%4,%5,%6,%7}, {%8,%9}, {%0,%1,%2,%3};\n"
        : "+f"(c[0]), "+f"(c[1]), "+f"(c[2]), "+f"(c[3])
        : "r"(a[0]), "r"(a[1]), "r"(a[2]), "r"(a[3]), "r"(b0), "r"(b1));
}
__device__ __forceinline__ uint32_t h2u(__half2 h) {
    return *reinterpret_cast<uint32_t*>(&h);
}
__device__ __forceinline__ uint32_t smaddr(const void* p) {
    return (uint32_t)__cvta_generic_to_shared(p);
}
#define CP16(dst, src) \
    asm volatile("cp.async.cg.shared.global [%0], [%1], 16;\n" :: "r"(dst), "l"(src))
#define CP4(dst, src)  \
    asm volatile("cp.async.ca.shared.global [%0], [%1], 4;\n"  :: "r"(dst), "l"(src))
#define CPCOMMIT() asm volatile("cp.async.commit_group;\n")
#define CPWAIT0()  asm volatile("cp.async.wait_group 0;\n")
#define CPWAIT1()  asm volatile("cp.async.wait_group 1;\n")

// ---------------- fused conversion + rope-table kernel -----------------------
__device__ __forceinline__ void kpair_one(const float* __restrict__ W,
                                          __half* __restrict__ Wh, int N, int i)
{
    int kk = i / N, n = i - kk * N;
    ((__half2*)Wh)[(size_t)kk * N + n] = __floats2half2_rn(
        W[(size_t)(2 * kk) * N + n], W[(size_t)(2 * kk + 1) * N + n]);
}

// grid 29312 x 256; all section sizes are exact multiples of 256.
__global__ void conv_all(
    const float* __restrict__ hidden, const float* __restrict__ Wq,
    const float* __restrict__ Wk, const float* __restrict__ Wv,
    const float* __restrict__ Wo, const float* __restrict__ Wg1,
    const float* __restrict__ Wg2, const int* __restrict__ pos,
    __half* __restrict__ hh, __half* __restrict__ wqh, __half* __restrict__ wkh,
    __half* __restrict__ wvh, __half* __restrict__ woh, __half* __restrict__ wgh,
    float* __restrict__ cosT, float* __restrict__ sinT)
{
    int bid = blockIdx.x, tid = threadIdx.x;
    if (bid < 8192) {                          // hidden fp32 -> fp16 natural
        int i = bid * 256 + tid;               // 2,097,152 float4
        float4 v = ((const float4*)hidden)[i];
        __half2* o = (__half2*)hh + (size_t)i * 2;
        o[0] = __floats2half2_rn(v.x, v.y);
        o[1] = __floats2half2_rn(v.z, v.w);
    } else if (bid < 16384) {                  // Wq k-pair
        kpair_one(Wq, wqh, 2048, (bid - 8192) * 256 + tid);
    } else if (bid < 18432) {                  // Wk
        kpair_one(Wk, wkh, 512, (bid - 16384) * 256 + tid);
    } else if (bid < 20480) {                  // Wv
        kpair_one(Wv, wvh, 512, (bid - 18432) * 256 + tid);
    } else if (bid < 28672) {                  // Wo
        kpair_one(Wo, woh, 2048, (bid - 20480) * 256 + tid);
    } else if (bid < 28800) {                  // gates pack: 128 blocks
        int i = (bid - 28672) * 256 + tid;
        int kk = i >> 5, n = i & 31;
        const float* W = (n < 16) ? Wg1 : Wg2;
        int col = n & 15;
        ((__half2*)wgh)[(size_t)kk * 32 + n] = __floats2half2_rn(
            W[(size_t)(2 * kk) * 16 + col], W[(size_t)(2 * kk + 1) * 16 + col]);
    } else {                                   // rope table: 512 blocks, 131072
        int idx = (bid - 28800) * 256 + tid;
        int s = idx >> 6, i = idx & 63;
        double p    = (double)pos[s];
        double invf = exp(-((double)i / 64.0) * log(10000.0));
        double ang  = p * invf;
        cosT[idx] = (float)cos(ang);
        sinT[idx] = (float)sin(ang);
    }
}

// ---------------- fp16 GEMM: C = A(Mx2048) @ W(2048xN) ----------------------
// BM=128 BN=128 BK=32, 4 warps (2x2), warp tile 64x64, mma m16n8k16
// stage (h2 words): A [128][20], B [16][136]. GSTG=4736 w.
#define GSTG 4736

__device__ __forceinline__ void gemm_issue_h(
    const __half* __restrict__ A, const __half* __restrict__ Wh,
    uint32_t* sa, int N, size_t m0, size_t n0, int k0, int tid)
{
    uint32_t* sb = sa + 2560;
#pragma unroll
    for (int j = 0; j < 4; j++) {                 // A: 512 CP16, 128 threads
        int idx = tid + j * 128;
        int r = idx >> 2, q = idx & 3;
        CP16(smaddr(sa + r * 20 + q * 4), A + (m0 + r) * HID + k0 + q * 8);
    }
#pragma unroll
    for (int j = 0; j < 4; j++) {                 // B: 512 CP16
        int idx = tid + j * 128;
        int r = idx >> 5, cc = idx & 31;
        CP16(smaddr(sb + r * 136 + cc * 4),
             Wh + ((size_t)((k0 >> 1) + r) * N + n0 + cc * 4) * 2);
    }
}

// MODE 0: C f32 natural. MODE 1: C half natural. MODE 2: C half V-interleaved.
template <int MODE>
__device__ __forceinline__ void gemm_body_h(
    const __half* __restrict__ A, const __half* __restrict__ Wh, void* Cv,
    int N, size_t m0, size_t n0, uint32_t* sm)
{
    const int tid  = threadIdx.x;
    const int lane = tid & 31;
    const int wid  = tid >> 5;          // 0..3
    const int g    = lane >> 2;
    const int c    = lane & 3;
    const int wm   = (wid >> 1) * 64;
    const int wn   = (wid & 1) * 64;

    float acc[4][8][4];
#pragma unroll
    for (int i = 0; i < 4; i++)
#pragma unroll
        for (int j = 0; j < 8; j++)
#pragma unroll
            for (int r = 0; r < 4; r++) acc[i][j][r] = 0.f;

    const int NIT = HID / 32;   // 64
    gemm_issue_h(A, Wh, sm + 0 * GSTG, N, m0, n0, 0, tid);  CPCOMMIT();
    gemm_issue_h(A, Wh, sm + 1 * GSTG, N, m0, n0, 32, tid); CPCOMMIT();

    for (int i = 0; i < NIT; i++) {
        CPWAIT1();
        __syncthreads();
        if (i + 2 < NIT)
            gemm_issue_h(A, Wh, sm + ((i + 2) % 3) * GSTG, N, m0, n0,
                         (i + 2) * 32, tid);
        CPCOMMIT();

        const uint32_t* sa = sm + (i % 3) * GSTG;
        const uint32_t* sb = sa + 2560;
#pragma unroll
        for (int kb = 0; kb < 2; kb++) {
            uint32_t af[4][4], bf[8][2];
#pragma unroll
            for (int mt = 0; mt < 4; mt++) {
                const uint32_t* ap = sa + (wm + mt * 16 + g) * 20 + kb * 8 + c;
                af[mt][0] = ap[0];
                af[mt][1] = ap[8 * 20];
                af[mt][2] = ap[4];
                af[mt][3] = ap[8 * 20 + 4];
            }
#pragma unroll
            for (int nt = 0; nt < 8; nt++) {
                const uint32_t* bp = sb + (kb * 8 + c) * 136 + wn + nt * 8 + g;
                bf[nt][0] = bp[0];
                bf[nt][1] = bp[4 * 136];
            }
#pragma unroll
            for (int mt = 0; mt < 4; mt++)
#pragma unroll
                for (int nt = 0; nt < 8; nt++)
                    mma16(acc[mt][nt], af[mt], bf[nt][0], bf[nt][1]);
        }
    }

    if (MODE == 0) {
        float* C = (float*)Cv;
#pragma unroll
        for (int mt = 0; mt < 4; mt++)
#pragma unroll
            for (int nt = 0; nt < 8; nt++) {
                size_t r  = m0 + wm + mt * 16 + g;
                size_t cc = n0 + wn + nt * 8 + 2 * c;
                *(float2*)&C[r * N + cc] =
                    make_float2(acc[mt][nt][0], acc[mt][nt][1]);
                *(float2*)&C[(r + 8) * N + cc] =
                    make_float2(acc[mt][nt][2], acc[mt][nt][3]);
            }
    } else if (MODE == 1) {
        __half* C = (__half*)Cv;
#pragma unroll
        for (int mt = 0; mt < 4; mt++)
#pragma unroll
            for (int nt = 0; nt < 8; nt++) {
                size_t r  = m0 + wm + mt * 16 + g;
                size_t cc = n0 + wn + nt * 8 + 2 * c;
                *(__half2*)&C[r * N + cc] =
                    __floats2half2_rn(acc[mt][nt][0], acc[mt][nt][1]);
                *(__half2*)&C[(r + 8) * N + cc] =
                    __floats2half2_rn(acc[mt][nt][2], acc[mt][nt][3]);
            }
    } else {
        __half* C = (__half*)Cv;
#pragma unroll
        for (int mt = 0; mt < 4; mt++)
#pragma unroll
            for (int nt = 0; nt < 8; nt++) {
                int ng  = (int)n0 + wn + nt * 8 + 2 * c;
                int kvh = ng >> 7, d = ng & 127;
#pragma unroll
                for (int p = 0; p < 2; p++) {
                    size_t tok = m0 + wm + mt * 16 + g + p * 8;
                    int b = (int)(tok >> 11), s = (int)(tok & 2047);
                    size_t base =
                        (((size_t)(b * NKV + kvh) * 1024 + (s >> 1)) * 128 + d) * 2
                        + (s & 1);
                    C[base]     = __float2half(acc[mt][nt][p * 2 + 0]);
                    C[base + 2] = __float2half(acc[mt][nt][p * 2 + 1]);
                }
            }
    }
}

// ---------------- gates body (128 threads, merged into qkv grid) -------------
__device__ __forceinline__ void gates_issue128(
    const __half* __restrict__ hh, const __half* __restrict__ WgT,
    uint32_t* sa, size_t m0, int k0, int tid)
{
    uint32_t* sb = sa + 2560;
#pragma unroll
    for (int j = 0; j < 4; j++) {                 // A: 512 CP16
        int idx = tid + j * 128;
        int r = idx >> 2, q = idx & 3;
        CP16(smaddr(sa + r * 20 + q * 4), hh + (m0 + r) * HID + k0 + q * 8);
    }
    {                                             // B: 128 CP16 ([16][32] h2)
        int r = tid >> 3, cc = tid & 7;
        CP16(smaddr(sb + r * 136 + cc * 4),
             WgT + ((size_t)((k0 >> 1) + r) * 32 + cc * 4) * 2);
    }
}

__device__ __forceinline__ void gates_body(
    const __half* __restrict__ hh, const __half* __restrict__ WgT,
    const float* __restrict__ bg1, const float* __restrict__ bg2,
    float* __restrict__ g1, float* __restrict__ g2,
    size_t m0, uint32_t* sm)
{
    const int tid  = threadIdx.x;
    const int lane = tid & 31;
    const int wid  = tid >> 5;          // 0..3, warp = 32 tokens (2 m-tiles)
    const int g    = lane >> 2;
    const int c    = lane & 3;

    float acc[2][4][4];
#pragma unroll
    for (int mt = 0; mt < 2; mt++)
#pragma unroll
        for (int j = 0; j < 4; j++)
#pragma unroll
            for (int r = 0; r < 4; r++) acc[mt][j][r] = 0.f;

    const int NIT = HID / 32;   // 64
    gates_issue128(hh, WgT, sm + 0 * GSTG, m0, 0, tid);  CPCOMMIT();
    gates_issue128(hh, WgT, sm + 1 * GSTG, m0, 32, tid); CPCOMMIT();

    for (int i = 0; i < NIT; i++) {
        CPWAIT1();
        __syncthreads();
        if (i + 2 < NIT)
            gates_issue128(hh, WgT, sm + ((i + 2) % 3) * GSTG, m0,
                           (i + 2) * 32, tid);
        CPCOMMIT();

        const uint32_t* sa = sm + (i % 3) * GSTG;
        const uint32_t* sb = sa + 2560;
#pragma unroll
        for (int kb = 0; kb < 2; kb++) {
#pragma unroll
            for (int mt = 0; mt < 2; mt++) {
                uint32_t af[4];
                const uint32_t* ap =
                    sa + (wid * 32 + mt * 16 + g) * 20 + kb * 8 + c;
                af[0] = ap[0];
                af[1] = ap[8 * 20];
                af[2] = ap[4];
                af[3] = ap[8 * 20 + 4];
#pragma unroll
                for (int nt = 0; nt < 4; nt++) {
                    const uint32_t* bp = sb + (kb * 8 + c) * 136 + nt * 8 + g;
                    mma16(acc[mt][nt], af, bp[0], bp[4 * 136]);
                }
            }
        }
    }

#pragma unroll
    for (int mt = 0; mt < 2; mt++)
#pragma unroll
        for (int nt = 0; nt < 4; nt++)
#pragma unroll
            for (int half = 0; half < 2; half++) {
                int n = nt * 8 + 2 * c + half;
                float b = (n < 16) ? bg1[n] : bg2[n - 16];
#pragma unroll
                for (int p = 0; p < 2; p++) {
                    size_t tok = m0 + wid * 32 + mt * 16 + g + p * 8;
                    float v = 1.f / (1.f + __expf(-(acc[mt][nt][p * 2 + half] + b)));
                    if (n < 16) g1[tok * NH + n]        = v;
                    else        g2[tok * NH + (n - 16)] = v;
                }
            }
}

// fused QKV + gates: grid (25, 32), 128 threads
__global__ __launch_bounds__(128, 2) void qkv_kernel(
    const __half* __restrict__ hidden_h,
    const __half* __restrict__ Wq_h, const __half* __restrict__ Wk_h,
    const __half* __restrict__ Wv_h, const __half* __restrict__ Wg_h,
    const float* __restrict__ bg1, const float* __restrict__ bg2,
    __half* __restrict__ qh, __half* __restrict__ kh, __half* __restrict__ vh,
    float* __restrict__ g1, float* __restrict__ g2)
{
    extern __shared__ uint32_t gsm[];
    int bx = blockIdx.x;
    size_t m0 = (size_t)blockIdx.y * 128;
    if (bx < 16)
        gemm_body_h<1>(hidden_h, Wq_h, qh, 2048, m0, (size_t)bx * 128, gsm);
    else if (bx < 20)
        gemm_body_h<1>(hidden_h, Wk_h, kh, 512, m0, (size_t)(bx - 16) * 128, gsm);
    else if (bx < 24)
        gemm_body_h<2>(hidden_h, Wv_h, vh, 512, m0, (size_t)(bx - 20) * 128, gsm);
    else
        gates_body(hidden_h, Wg_h, bg1, bg2, g1, g2, m0, gsm);
}

__global__ __launch_bounds__(128, 2) void out_kernel(
    const __half* __restrict__ att_h, const __half* __restrict__ Wo_h,
    float* __restrict__ out)
{
    extern __shared__ uint32_t gsm[];
    gemm_body_h<0>(att_h, Wo_h, out, 2048, (size_t)blockIdx.y * 128,
                   (size_t)blockIdx.x * 128, gsm);
}

// ---------------- fused vectorized in-place fp16 RoPE (q + k, 8 elems/thr) ---
__global__ void rope_both_h(__half* __restrict__ qh, __half* __restrict__ kh,
                            const float* __restrict__ cosT,
                            const float* __restrict__ sinT)
{
    int idx = blockIdx.x * blockDim.x + threadIdx.x;
    const int qtot = M_TOK * NH * 16;          // 1,048,576
    __half* x;
    int heads;
    if (idx < qtot) {
        x = qh; heads = NH;
    } else {
        idx -= qtot;
        x = kh; heads = NKV;
    }
    int i4 = (idx & 15) * 4;
    int h  = (idx >> 4) % heads;
    int m  = idx / (heads * 16);
    int s  = m & (S_LEN - 1);
    float4 cv = *(const float4*)&cosT[s * 64 + i4];
    float4 sn = *(const float4*)&sinT[s * 64 + i4];
    __half* p = x + ((size_t)m * heads + h) * HD;
    __half2 lo0 = *(__half2*)&p[i4],      lo1 = *(__half2*)&p[i4 + 2];
    __half2 hi0 = *(__half2*)&p[i4 + 64], hi1 = *(__half2*)&p[i4 + 66];
    float a0 = __half2float(lo0.x), a1 = __half2float(lo0.y);
    float a2 = __half2float(lo1.x), a3 = __half2float(lo1.y);
    float b0 = __half2float(hi0.x), b1 = __half2float(hi0.y);
    float b2 = __half2float(hi1.x), b3 = __half2float(hi1.y);
    *(__half2*)&p[i4]      = __floats2half2_rn(a0 * cv.x - b0 * sn.x,
                                               a1 * cv.y - b1 * sn.y);
    *(__half2*)&p[i4 + 2]  = __floats2half2_rn(a2 * cv.z - b2 * sn.z,
                                               a3 * cv.w - b3 * sn.w);
    *(__half2*)&p[i4 + 64] = __floats2half2_rn(b0 * cv.x + a0 * sn.x,
                                               b1 * cv.y + a1 * sn.y);
    *(__half2*)&p[i4 + 66] = __floats2half2_rn(b2 * cv.z + a2 * sn.z,
                                               b3 * cv.w + a3 * sn.w);
}

// ---------------- fp16 flash attention (proven R12/R15 smem-P version) -------
// smem h2 words: stage s: K at s*8704 ([64][68]), V at +4352 ([32][136]);
// P at 17408 ([128][36]); g2 f32 at 22016 ([2][64]). total 22144 w = 88576 B.
__device__ __forceinline__ void kv_issue_h(
    const __half* __restrict__ kh, const __half* __restrict__ vh,
    const float* __restrict__ g2, uint32_t* smw, int stage,
    int b, int kt, int kvh, int h, int tid)
{
    uint32_t* Kst = smw + stage * 8704;
    uint32_t* Vst = Kst + 4352;
    float*    g2d = (float*)(smw + 22016) + stage * 64;
#pragma unroll
    for (int j = 0; j < 4; j++) {
        int idx = tid + j * 256;
        int r = idx >> 4, cc = idx & 15;
        size_t tok = (size_t)(b * S_LEN + kt * 64 + r);
        CP16(smaddr(Kst + r * 68 + cc * 4), kh + (tok * NKV + kvh) * HD + cc * 8);
    }
#pragma unroll
    for (int j = 0; j < 4; j++) {
        int idx = tid + j * 256;
        int r = idx >> 5, cc = idx & 31;
        size_t sp = (size_t)(b * NKV + kvh) * 1024 + kt * 32 + r;
        CP16(smaddr(Vst + r * 136 + cc * 4), vh + sp * 256 + cc * 8);
    }
    if (tid < 64) {
        size_t tok = (size_t)(b * S_LEN + kt * 64 + tid);
        CP4(smaddr(g2d + tid), g2 + tok * NH + h);
    }
}

__global__ __launch_bounds__(256) void flash_h(
    const __half* __restrict__ qh, const __half* __restrict__ kh,
    const __half* __restrict__ vh,
    const float* __restrict__ g1, const float* __restrict__ g2,
    const float* __restrict__ gamma, const float* __restrict__ beta,
    __half* __restrict__ att)
{
    const int qt  = (int)(gridDim.x - 1 - blockIdx.x);   // LPT: big blocks first
    const int bh  = blockIdx.y;
    const int b   = bh >> 4;
    const int h   = bh & 15;
    const int kvh = h >> 2;
    const int tid = threadIdx.x;
    const int lane = tid & 31;
    const int wid  = tid >> 5;
    const int g    = lane >> 2;
    const int c    = lane & 3;
    const int q0   = qt * 128;

    extern __shared__ uint32_t smw[];
    uint32_t* Ps = smw + 17408;

    const float scale = 0.08838834764831845f;
    const int nkt = 2 * (qt + 1);

    kv_issue_h(kh, vh, g2, smw, 0, b, 0, kvh, h, tid);
    CPCOMMIT();
    {
        uint32_t* Qt = smw + 8704;
#pragma unroll
        for (int j = 0; j < 8; j++) {
            int idx = tid + j * 256;
            int r = idx >> 4, cc = idx & 15;
            CP16(smaddr(Qt + r * 68 + cc * 4),
                 qh + ((size_t)(b * S_LEN + q0 + r) * NH + h) * HD + cc * 8);
        }
    }
    CPCOMMIT();
    CPWAIT0();
    __syncthreads();

    uint32_t qf[8][4];
    {
        const uint32_t* Qt = smw + 8704;
#pragma unroll
        for (int kb = 0; kb < 8; kb++) {
            const uint32_t* qp = Qt + (wid * 16 + g) * 68 + kb * 8 + c;
            qf[kb][0] = qp[0];
            qf[kb][1] = qp[8 * 68];
            qf[kb][2] = qp[4];
            qf[kb][3] = qp[8 * 68 + 4];
        }
    }
    __syncthreads();

    float oacc[16][4];
#pragma unroll
    for (int nt = 0; nt < 16; nt++)
#pragma unroll
        for (int r = 0; r < 4; r++) oacc[nt][r] = 0.f;
    float m_r0 = -1e30f, m_r1 = -1e30f, l_r0 = 0.f, l_r1 = 0.f;

    for (int kt = 0; kt < nkt; kt++) {
        if (kt + 1 < nkt)
            kv_issue_h(kh, vh, g2, smw, (kt + 1) & 1, b, kt + 1, kvh, h, tid);
        CPCOMMIT();

        const uint32_t* Kst = smw + (kt & 1) * 8704;
        const uint32_t* Vst = Kst + 4352;
        const float*    g2p = (const float*)(smw + 22016) + (kt & 1) * 64;
        const int k0 = kt * 64;

        float s[8][4];
#pragma unroll
        for (int nt = 0; nt < 8; nt++)
#pragma unroll
            for (int r = 0; r < 4; r++) s[nt][r] = 0.f;
#pragma unroll
        for (int kb = 0; kb < 8; kb++)
#pragma unroll
            for (int nt = 0; nt < 8; nt++) {
                const uint32_t* kp = Kst + (nt * 8 + g) * 68 + kb * 8 + c;
                mma16(s[nt], qf[kb], kp[0], kp[4]);
            }
#pragma unroll
        for (int nt = 0; nt < 8; nt++)
#pragma unroll
            for (int r = 0; r < 4; r++) s[nt][r] *= scale;

        if (kt >= 2 * qt) {
            const int r0 = q0 + wid * 16 + g, r1 = r0 + 8;
#pragma unroll
            for (int nt = 0; nt < 8; nt++) {
                int col = k0 + nt * 8 + 2 * c;
                if (col     > r0) s[nt][0] = -1e30f;
                if (col + 1 > r0) s[nt][1] = -1e30f;
                if (col     > r1) s[nt][2] = -1e30f;
                if (col + 1 > r1) s[nt][3] = -1e30f;
            }
        }

        float mx0 = -1e30f, mx1 = -1e30f;
#pragma unroll
        for (int nt = 0; nt < 8; nt++) {
            mx0 = fmaxf(mx0, fmaxf(s[nt][0], s[nt][1]));
            mx1 = fmaxf(mx1, fmaxf(s[nt][2], s[nt][3]));
        }
#pragma unroll
        for (int off = 1; off <= 2; off <<= 1) {
            mx0 = fmaxf(mx0, __shfl_xor_sync(0xffffffffu, mx0, off));
            mx1 = fmaxf(mx1, __shfl_xor_sync(0xffffffffu, mx1, off));
        }
        float mn0 = fmaxf(m_r0, mx0), mn1 = fmaxf(m_r1, mx1);
        float sum0 = 0.f, sum1 = 0.f;
#pragma unroll
        for (int nt = 0; nt < 8; nt++) {
            s[nt][0] = __expf(s[nt][0] - mn0);
            s[nt][1] = __expf(s[nt][1] - mn0);
            s[nt][2] = __expf(s[nt][2] - mn1);
            s[nt][3] = __expf(s[nt][3] - mn1);
            sum0 += s[nt][0] + s[nt][1];
            sum1 += s[nt][2] + s[nt][3];
        }
#pragma unroll
        for (int off = 1; off <= 2; off <<= 1) {
            sum0 += __shfl_xor_sync(0xffffffffu, sum0, off);
            sum1 += __shfl_xor_sync(0xffffffffu, sum1, off);
        }
        float a0 = __expf(m_r0 - mn0), a1 = __expf(m_r1 - mn1);
        m_r0 = mn0; m_r1 = mn1;
        l_r0 = l_r0 * a0 + sum0;
        l_r1 = l_r1 * a1 + sum1;
#pragma unroll
        for (int nt = 0; nt < 16; nt++) {
            oacc[nt][0] *= a0; oacc[nt][1] *= a0;
            oacc[nt][2] *= a1; oacc[nt][3] *= a1;
        }

        {
            const int r0 = wid * 16 + g;
#pragma unroll
            for (int nt = 0; nt < 8; nt++) {
                int col = nt * 8 + 2 * c;
                float w0 = g2p[col], w1 = g2p[col + 1];
                Ps[r0 * 36 + nt * 4 + c] =
                    h2u(__floats2half2_rn(s[nt][0] * w0, s[nt][1] * w1));
                Ps[(r0 + 8) * 36 + nt * 4 + c] =
                    h2u(__floats2half2_rn(s[nt][2] * w0, s[nt][3] * w1));
            }
        }
        __syncwarp();

#pragma unroll
        for (int kb = 0; kb < 4; kb++) {
            uint32_t pf[4];
            const uint32_t* pp = Ps + (wid * 16 + g) * 36 + kb * 8 + c;
            pf[0] = pp[0];
            pf[1] = pp[8 * 36];
            pf[2] = pp[4];
            pf[3] = pp[8 * 36 + 4];
#pragma unroll
            for (int nt = 0; nt < 16; nt++) {
                const uint32_t* vp = Vst + (kb * 8 + c) * 136 + nt * 8 + g;
                mma16(oacc[nt], pf, vp[0], vp[4 * 136]);
            }
        }

        if (kt + 1 < nkt) {
            CPWAIT0();
            __syncthreads();
        }
    }
    __syncthreads();

    float* gb = (float*)Ps;
    if (tid < 128) {
        gb[tid]       = gamma[tid];
        gb[128 + tid] = beta[tid];
    }
    __syncthreads();

    float inv0 = 1.f / l_r0, inv1 = 1.f / l_r1;
    float su0 = 0.f, sq0 = 0.f, su1 = 0.f, sq1 = 0.f;
#pragma unroll
    for (int nt = 0; nt < 16; nt++) {
        oacc[nt][0] *= inv0; oacc[nt][1] *= inv0;
        oacc[nt][2] *= inv1; oacc[nt][3] *= inv1;
        su0 += oacc[nt][0] + oacc[nt][1];
        sq0 += oacc[nt][0] * oacc[nt][0] + oacc[nt][1] * oacc[nt][1];
        su1 += oacc[nt][2] + oacc[nt][3];
        sq1 += oacc[nt][2] * oacc[nt][2] + oacc[nt][3] * oacc[nt][3];
    }
#pragma unroll
    for (int off = 1; off <= 2; off <<= 1) {
        su0 += __shfl_xor_sync(0xffffffffu, su0, off);
        sq0 += __shfl_xor_sync(0xffffffffu, sq0, off);
        su1 += __shfl_xor_sync(0xffffffffu, su1, off);
        sq1 += __shfl_xor_sync(0xffffffffu, sq1, off);
    }
    float mu0 = su0 * (1.f / 128.f), mu1 = su1 * (1.f / 128.f);
    float rs0 = rsqrtf(sq0 * (1.f / 128.f) - mu0 * mu0 + 1e-5f);
    float rs1 = rsqrtf(sq1 * (1.f / 128.f) - mu1 * mu1 + 1e-5f);

    const int r0 = q0 + wid * 16 + g, r1 = r0 + 8;
    float gv0 = g1[((size_t)(b * S_LEN + r0)) * NH + h];
    float gv1 = g1[((size_t)(b * S_LEN + r1)) * NH + h];
    size_t base0 = ((size_t)(b * S_LEN + r0)) * (NH * HD) + h * HD;
    size_t base1 = ((size_t)(b * S_LEN + r1)) * (NH * HD) + h * HD;
#pragma unroll
    for (int nt = 0; nt < 16; nt++) {
        int col = nt * 8 + 2 * c;
        float ga = gb[col], gba = gb[128 + col];
        float gc = gb[col + 1], gbc = gb[128 + col + 1];
        *(__half2*)&att[base0 + col] = __floats2half2_rn(
            ((oacc[nt][0] - mu0) * rs0 * ga + gba) * gv0,
            ((oacc[nt][1] - mu0) * rs0 * gc + gbc) * gv0);
        *(__half2*)&att[base1 + col] = __floats2half2_rn(
            ((oacc[nt][2] - mu1) * rs1 * ga + gba) * gv1,
            ((oacc[nt][3] - mu1) * rs1 * gc + gbc) * gv1);
    }
}

// ---------------- launch ----------------------------------------------------
extern "C" void kernel_launch(void* const* d_in, const int* in_sizes, int n_in,
                              void* d_out, int out_size)
{
    const float* hidden = (const float*)d_in[0];
    const int*   pos    = (const int*)d_in[1];
    const float* Wq     = (const float*)d_in[2];
    const float* Wk     = (const float*)d_in[3];
    const float* Wv     = (const float*)d_in[4];
    const float* Wo     = (const float*)d_in[5];
    const float* Wg1    = (const float*)d_in[6];
    const float* bg1    = (const float*)d_in[7];
    const float* Wg2    = (const float*)d_in[8];
    const float* bg2    = (const float*)d_in[9];
    const float* gamma  = (const float*)d_in[10];
    const float* beta   = (const float*)d_in[11];
    float* out = (float*)d_out;

    float *g1, *g2, *cosT, *sinT;
    __half *hh, *wqh, *wkh, *wvh, *woh, *wgh, *qh, *kh, *vh, *atth;
    cudaGetSymbolAddress((void**)&g1,   g_g1);
    cudaGetSymbolAddress((void**)&g2,   g_g2);
    cudaGetSymbolAddress((void**)&cosT, g_cosT);
    cudaGetSymbolAddress((void**)&sinT, g_sinT);
    cudaGetSymbolAddress((void**)&hh,   g_hidden_h);
    cudaGetSymbolAddress((void**)&wqh,  g_Wq_h);
    cudaGetSymbolAddress((void**)&wkh,  g_Wk_h);
    cudaGetSymbolAddress((void**)&wvh,  g_Wv_h);
    cudaGetSymbolAddress((void**)&woh,  g_Wo_h);
    cudaGetSymbolAddress((void**)&wgh,  g_Wg_h);
    cudaGetSymbolAddress((void**)&qh,   g_qh);
    cudaGetSymbolAddress((void**)&kh,   g_kh);
    cudaGetSymbolAddress((void**)&vh,   g_vh);
    cudaGetSymbolAddress((void**)&atth, g_att_h);

    // 0) fused conversions + rope table
    conv_all<<<29312, 256>>>(hidden, Wq, Wk, Wv, Wo, Wg1, Wg2, pos,
                             hh, wqh, wkh, wvh, woh, wgh, cosT, sinT);

    const int gemm_smem = 3 * GSTG * 4;   // 56832 B
    cudaFuncSetAttribute(qkv_kernel, cudaFuncAttributeMaxDynamicSharedMemorySize,
                         gemm_smem);
    cudaFuncSetAttribute(out_kernel, cudaFuncAttributeMaxDynamicSharedMemorySize,
                         gemm_smem);

    // 1) fused Q/K/V projections + gates (fp16 outputs)
    qkv_kernel<<<dim3(25, 32), 128, gemm_smem>>>(
        hh, wqh, wkh, wvh, wgh, bg1, bg2, qh, kh, vh, g1, g2);

    // 2) fused in-place fp16 RoPE (q + k in one launch)
    rope_both_h<<<(M_TOK * (NH + NKV) * 16) / 256, 256>>>(qh, kh, cosT, sinT);

    // 3) fp16 flash attention (proven smem-P version, LPT block order)
    const int flash_smem = 22144 * 4;     // 88576 B
    cudaFuncSetAttribute(flash_h, cudaFuncAttributeMaxDynamicSharedMemorySize,
                         flash_smem);
    flash_h<<<dim3(S_LEN / 128, B_SZ * NH), 256, flash_smem>>>(
        qh, kh, vh, g1, g2, gamma, beta, atth);

    // 4) output projection
    out_kernel<<<dim3(16, 32), 128, gemm_smem>>>(atth, woh, out);
}